// round 2
// baseline (speedup 1.0000x reference)
#include <cuda_runtime.h>

#define NB     32
#define NT     256
#define NITER  200
#define LROWS  8192

// err = 2^(-2*bits), bits = {2,3,4,5,6,8,10,12}
__constant__ float c_err[8] = {
    6.25e-2f, 1.5625e-2f, 3.90625e-3f, 9.765625e-4f,
    2.44140625e-4f, 1.52587890625e-5f, 9.5367431640625e-7f, 5.9604644775390625e-8f
};

__device__ float g_sum_n;
__device__ float g_inv_sens;
// ring of 2 slots; 32 blocks * 8 warps * 8 cols = 2048 partials per slot
__device__ float g_part[2][2048];

__device__ __forceinline__ float ld_cg(const float* p) {
    float v;
    asm volatile("ld.global.cg.f32 %0, [%1];" : "=f"(v) : "l"(p) : "memory");
    return v;
}
__device__ __forceinline__ void st_cg(float* p, float v) {
    asm volatile("st.global.cg.f32 [%0], %1;" :: "l"(p), "f"(v) : "memory");
}
__device__ __forceinline__ float ex2f(float x) {
    float y; asm("ex2.approx.f32 %0, %1;" : "=f"(y) : "f"(x)); return y;
}
__device__ __forceinline__ float lg2f(float x) {
    float y; asm("lg2.approx.f32 %0, %1;" : "=f"(y) : "f"(x)); return y;
}

// ---------------------------------------------------------------------------
// Pre-kernel: input sums + ring init (-0.0 => sign bit 1) for graph replays
// ---------------------------------------------------------------------------
__global__ void da_pre_kernel(const float* __restrict__ n_raw,
                              const float* __restrict__ sens_raw) {
    __shared__ float s1[NT / 32], s2[NT / 32];
    int t = threadIdx.x;
    float sn = 0.f, ss = 0.f;
    for (int i = t; i < LROWS; i += NT) { sn += n_raw[i]; ss += sens_raw[i]; }
#pragma unroll
    for (int o = 16; o; o >>= 1) {
        sn += __shfl_xor_sync(0xffffffffu, sn, o);
        ss += __shfl_xor_sync(0xffffffffu, ss, o);
    }
    if ((t & 31) == 0) { s1[t >> 5] = sn; s2[t >> 5] = ss; }
    __syncthreads();
    if (t == 0) {
        float a = 0.f, b = 0.f;
#pragma unroll
        for (int w = 0; w < NT / 32; w++) { a += s1[w]; b += s2[w]; }
        g_sum_n    = a * 1e5f + 1e3f * (float)LROWS;
        g_inv_sens = 1.0f / (b + 1e-12f);
    }
    float* ring = (float*)g_part;
    const float neg0 = __int_as_float(0x80000000u);
    for (int i = t; i < 2 * 2048; i += NT) ring[i] = neg0;
}

// ---------------------------------------------------------------------------
// Main kernel: 32 blocks x 256 threads, one row per thread (8 cols in regs).
// Data-as-flag global exchange: 1 L2 round trip per Sinkhorn iteration.
// ---------------------------------------------------------------------------
__global__ void __launch_bounds__(NT, 1)
da_main_kernel(const float* __restrict__ theta,
               const float* __restrict__ phi,
               const float* __restrict__ sens_raw,
               const float* __restrict__ n_raw,
               float* __restrict__ out) {
    const int tid  = threadIdx.x;
    const int lane = tid & 31;
    const int warp = tid >> 5;
    const int row  = blockIdx.x * NT + tid;
    const int ws   = blockIdx.x * 8 + warp;       // global warp slot 0..255
    const unsigned FULL = 0xffffffffu;
    const float L2E = 1.4426950408889634f;

    __shared__ float sred[8][8];

    // log_b in base-2: lb2[j] = (phi[j] - logsumexp(phi)) * log2(e)
    float lb2[8];
    {
        float q[8];
#pragma unroll
        for (int j = 0; j < 8; j++) q[j] = phi[j] * L2E;
        float m = fmaxf(fmaxf(fmaxf(q[0], q[1]), fmaxf(q[2], q[3])),
                        fmaxf(fmaxf(q[4], q[5]), fmaxf(q[6], q[7])));
        float s = 0.f;
#pragma unroll
        for (int j = 0; j < 8; j++) s += ex2f(q[j] - m);
        float ls = lg2f(s);
#pragma unroll
        for (int j = 0; j < 8; j++) lb2[j] = q[j] - m - ls;
    }

    // K in base-2: K2 = -(C - theta)/eps * log2e = (theta - C) * 50 * log2e
    const float inv_sumn = 1.0f / g_sum_n;
    float n  = n_raw[row] * 1e5f + 1e3f;
    float a  = n * inv_sumn;
    float cs = n * sens_raw[row] * g_inv_sens;
    const float SC = 50.0f * L2E;
    float K2[8];
    {
        const float4* t4 = (const float4*)theta;
        float4 ta = t4[row * 2], tb = t4[row * 2 + 1];
        K2[0] = (ta.x - cs * c_err[0]) * SC;
        K2[1] = (ta.y - cs * c_err[1]) * SC;
        K2[2] = (ta.z - cs * c_err[2]) * SC;
        K2[3] = (ta.w - cs * c_err[3]) * SC;
        K2[4] = (tb.x - cs * c_err[4]) * SC;
        K2[5] = (tb.y - cs * c_err[5]) * SC;
        K2[6] = (tb.z - cs * c_err[6]) * SC;
        K2[7] = (tb.w - cs * c_err[7]) * SC;
    }

    float G2[8], Gm1[8], p[8], T[8];
#pragma unroll
    for (int j = 0; j < 8; j++) {
        G2[j]  = 0.f;
        Gm1[j] = __int_as_float(0x7f000000u);  // sentinel, never equal
        T[j]   = 1.f;
    }

    for (int it = 0; it < NITER; ++it) {
        const int      slot = it & 1;
        const unsigned esgn = (unsigned)((it >> 1) & 1);

        // ---- row step (all in-thread): f-normalize row, P entries
        float x[8];
#pragma unroll
        for (int j = 0; j < 8; j++) x[j] = K2[j] + G2[j];
        float m2 = fmaxf(fmaxf(fmaxf(x[0], x[1]), fmaxf(x[2], x[3])),
                         fmaxf(fmaxf(x[4], x[5]), fmaxf(x[6], x[7])));
        float S = 0.f;
#pragma unroll
        for (int j = 0; j < 8; j++) { p[j] = ex2f(x[j] - m2); S += p[j]; }
        float ar = __fdividef(a, S);
#pragma unroll
        for (int j = 0; j < 8; j++) p[j] *= ar;   // P_ij = exp(K+f+g_old)

        // ---- butterfly transpose-reduce: warp col sums -> lane holds col (lane&7)
        float z;
        {
            float s0 = __shfl_xor_sync(FULL, p[0], 4);
            float s1 = __shfl_xor_sync(FULL, p[1], 4);
            float s2 = __shfl_xor_sync(FULL, p[2], 4);
            float s3 = __shfl_xor_sync(FULL, p[3], 4);
            float s4 = __shfl_xor_sync(FULL, p[4], 4);
            float s5 = __shfl_xor_sync(FULL, p[5], 4);
            float s6 = __shfl_xor_sync(FULL, p[6], 4);
            float s7 = __shfl_xor_sync(FULL, p[7], 4);
            bool hi4 = (lane & 4) != 0;
            float u0 = hi4 ? (p[4] + s4) : (p[0] + s0);
            float u1 = hi4 ? (p[5] + s5) : (p[1] + s1);
            float u2 = hi4 ? (p[6] + s6) : (p[2] + s2);
            float u3 = hi4 ? (p[7] + s7) : (p[3] + s3);
            float r0 = __shfl_xor_sync(FULL, u0, 2);
            float r1 = __shfl_xor_sync(FULL, u1, 2);
            float r2 = __shfl_xor_sync(FULL, u2, 2);
            float r3 = __shfl_xor_sync(FULL, u3, 2);
            bool hi2 = (lane & 2) != 0;
            float w0 = hi2 ? (u2 + r2) : (u0 + r0);
            float w1 = hi2 ? (u3 + r3) : (u1 + r1);
            float q0 = __shfl_xor_sync(FULL, w0, 1);
            float q1 = __shfl_xor_sync(FULL, w1, 1);
            z = (lane & 1) ? (w1 + q1) : (w0 + q0);
            z += __shfl_xor_sync(FULL, z, 8);
            z += __shfl_xor_sync(FULL, z, 16);
        }

        // ---- publish warp partial (data IS the flag; sign encodes phase)
        if (lane < 8) {
            float val = z + 1e-35f;                 // guarantee nonzero, negligible bias
            st_cg(&g_part[slot][(ws << 3) + lane], esgn ? -val : val);
        }

        // ---- poll all 256 warp slots (8 values per thread, index = tid + 256k)
        float    v[8];
        unsigned mask = 0;
        const float* bp = g_part[slot];
        while (mask != 0xffu) {
#pragma unroll
            for (int k = 0; k < 8; k++) {
                if (!((mask >> k) & 1u)) {
                    float xv = ld_cg(bp + tid + (k << 8));
                    if ((__float_as_uint(xv) >> 31) == esgn) {
                        v[k] = fabsf(xv);
                        mask |= (1u << k);
                    }
                }
            }
        }
        float csum = ((v[0] + v[1]) + (v[2] + v[3])) + ((v[4] + v[5]) + (v[6] + v[7]));
        csum += __shfl_xor_sync(FULL, csum, 8);
        csum += __shfl_xor_sync(FULL, csum, 16);
        if (lane < 8) sred[warp][lane] = csum;
        __syncthreads();

        // ---- final combine + g update (bitwise identical in every thread)
        bool conv = ((it & 1) == 1);
#pragma unroll
        for (int j = 0; j < 8; j++) {
            float Tj = ((sred[0][j] + sred[1][j]) + (sred[2][j] + sred[3][j]))
                     + ((sred[4][j] + sred[5][j]) + (sred[6][j] + sred[7][j]));
            T[j] = Tj;
            float gn = lb2[j] + G2[j] - lg2f(fmaxf(Tj, 1e-37f));
            conv = conv && (__float_as_uint(gn) == __float_as_uint(Gm1[j]));
            Gm1[j] = G2[j];
            G2[j]  = gn;
        }
        // period-2 exact fixed point with matching parity: all remaining
        // iterations are exact no-ops; uniform across the whole grid.
        if (conv) break;
        // no second __syncthreads: next STS to sred is data-dependent on every
        // thread's read of sred this iteration (via gnew -> p -> shuffles -> poll)
    }

    // ---- final plan: P = p * exp2(Gfin - Gprev); total = sum_j T_j * ed_j
    float tot = 0.f, ed[8];
#pragma unroll
    for (int j = 0; j < 8; j++) { ed[j] = ex2f(G2[j] - Gm1[j]); tot += T[j] * ed[j]; }
    float inv = 1.0f / (tot + 1e-40f);

    float4 o0, o1;
    o0.x = p[0] * ed[0] * inv;  o0.y = p[1] * ed[1] * inv;
    o0.z = p[2] * ed[2] * inv;  o0.w = p[3] * ed[3] * inv;
    o1.x = p[4] * ed[4] * inv;  o1.y = p[5] * ed[5] * inv;
    o1.z = p[6] * ed[6] * inv;  o1.w = p[7] * ed[7] * inv;
    float4* out4 = (float4*)out;
    out4[row * 2]     = o0;
    out4[row * 2 + 1] = o1;
}

// ---------------------------------------------------------------------------
extern "C" void kernel_launch(void* const* d_in, const int* in_sizes, int n_in,
                              void* d_out, int out_size) {
    const float* theta    = (const float*)d_in[0];
    const float* phi      = (const float*)d_in[1];
    const float* sens_raw = (const float*)d_in[2];
    const float* n_raw    = (const float*)d_in[3];
    float*       out      = (float*)d_out;

    da_pre_kernel<<<1, NT>>>(n_raw, sens_raw);
    da_main_kernel<<<NB, NT>>>(theta, phi, sens_raw, n_raw, out);
}